// round 1
// baseline (speedup 1.0000x reference)
#include <cuda_runtime.h>
#include <cstdint>

#define NODE_DIM 64
#define MSG_DIM  64
#define PROP_DIM 32
#define HIDDEN   128
#define T_DIM    8
#define S_DIM    16

#define MAX_V    10000
#define AS_STRIDE 68   // 64 + 4 pad: makes all mma A-fragment LDS conflict-free

// Scratch for per-node base vector: base[v][h] = h_t[v].Wh + theta[v].Wp + b1
__device__ float g_base[MAX_V * HIDDEN];

__device__ __forceinline__ float tf32_rna(float x) {
    uint32_t u;
    asm("cvt.rna.tf32.f32 %0, %1;" : "=r"(u) : "f"(x));
    return __uint_as_float(u);
}

#define MMA_TF32(D, a0, a1, a2, a3, b0, b1)                                   \
    asm volatile(                                                             \
        "mma.sync.aligned.m16n8k8.row.col.f32.tf32.tf32.f32 "                 \
        "{%0,%1,%2,%3}, {%4,%5,%6,%7}, {%8,%9}, {%0,%1,%2,%3};"               \
        : "+f"(D[0]), "+f"(D[1]), "+f"(D[2]), "+f"(D[3])                      \
        : "r"(a0), "r"(a1), "r"(a2), "r"(a3), "r"(b0), "r"(b1))

// ---------------------------------------------------------------------------
// Kernel 1: base[v][h] = b1[h] + sum_d h_t[v,d]*W1[d,h] + sum_p theta[v,p]*W1[129+p,h]
// W1 rows: Wh = 0..63, Wm = 64..127, Wt = 128, Wp = 129..160
// ---------------------------------------------------------------------------
__global__ __launch_bounds__(256) void base_kernel(
    const float* __restrict__ h_t,
    const float* __restrict__ theta,
    const float* __restrict__ W1,
    const float* __restrict__ b1,
    int V)
{
    extern __shared__ float sm1[];
    float* Wsm  = sm1;               // 96*128 floats (Wh rows then Wp rows)
    float* b1sm = sm1 + 96 * 128;    // 128
    float* hsm  = b1sm + 128;        // 16*96  ([v][d<64]=h_t, [v][64+p]=theta)

    const int tid = threadIdx.x;

    for (int i = tid; i < 96 * 128; i += 256) {
        int r = i >> 7;
        int c = i & 127;
        int gr = (r < NODE_DIM) ? r : (NODE_DIM + MSG_DIM + 1 + (r - NODE_DIM));
        Wsm[i] = W1[gr * HIDDEN + c];
    }
    if (tid < HIDDEN) b1sm[tid] = b1[tid];

    const int v0 = blockIdx.x * 64;

    for (int pass = 0; pass < 4; ++pass) {
        __syncthreads();  // (pass 0: covers Wsm; later: protects hsm reuse)
        const int vp = v0 + pass * 16;

        for (int i = tid; i < 16 * 64; i += 256) {
            int v = i >> 6, d = i & 63;
            hsm[v * 96 + d] = (vp + v < V) ? h_t[(size_t)(vp + v) * NODE_DIM + d] : 0.f;
        }
        for (int i = tid; i < 16 * 32; i += 256) {
            int v = i >> 5, p = i & 31;
            hsm[v * 96 + 64 + p] = (vp + v < V) ? theta[(size_t)(vp + v) * PROP_DIM + p] : 0.f;
        }
        __syncthreads();

        const int h4 = (tid & 31) * 4;    // 4 consecutive hidden cols
        const int vl = (tid >> 5) * 2;    // 2 nodes per thread

        float4 acc0 = *(const float4*)&b1sm[h4];
        float4 acc1 = acc0;
        const float* hv0 = &hsm[vl * 96];
        const float* hv1 = hv0 + 96;

        #pragma unroll 8
        for (int d = 0; d < 96; ++d) {
            float4 ww = *(const float4*)&Wsm[d * 128 + h4];
            float x0 = hv0[d], x1 = hv1[d];
            acc0.x = fmaf(x0, ww.x, acc0.x);
            acc0.y = fmaf(x0, ww.y, acc0.y);
            acc0.z = fmaf(x0, ww.z, acc0.z);
            acc0.w = fmaf(x0, ww.w, acc0.w);
            acc1.x = fmaf(x1, ww.x, acc1.x);
            acc1.y = fmaf(x1, ww.y, acc1.y);
            acc1.z = fmaf(x1, ww.z, acc1.z);
            acc1.w = fmaf(x1, ww.w, acc1.w);
        }
        if (vp + vl < V)
            *(float4*)&g_base[(size_t)(vp + vl) * HIDDEN + h4] = acc0;
        if (vp + vl + 1 < V)
            *(float4*)&g_base[(size_t)(vp + vl + 1) * HIDDEN + h4] = acc1;
    }
}

// ---------------------------------------------------------------------------
// Kernel 2: for each group g = v*T + t (16 rows s=0..15):
//   D(16x128) = M(16x64) @ Wm(64x128)   via mma.sync tf32
//   logit[row] = sum_c relu(D + base[v][c] + tau[t]*Wt[c]) * W2[c] + b2
// ---------------------------------------------------------------------------

__device__ __forceinline__ void stage_loads(
    const float* __restrict__ messages, int g, int tid,
    float4& r0, float4& r1, float4& rb)
{
    const float4* src = (const float4*)(messages + (size_t)g * (S_DIM * MSG_DIM));
    r0 = src[tid];
    r1 = src[tid + 128];
    if (tid < 32)
        rb = ((const float4*)(g_base + (size_t)(g >> 3) * HIDDEN))[tid];
}

__device__ __forceinline__ void stage_store(
    float* Asb, float* bsb, int tid, float4 r0, float4 r1, float4 rb)
{
    const int j0 = tid, j1 = tid + 128;
    float4 c0 = make_float4(tf32_rna(r0.x), tf32_rna(r0.y), tf32_rna(r0.z), tf32_rna(r0.w));
    float4 c1 = make_float4(tf32_rna(r1.x), tf32_rna(r1.y), tf32_rna(r1.z), tf32_rna(r1.w));
    *(float4*)&Asb[(j0 >> 4) * AS_STRIDE + (j0 & 15) * 4] = c0;
    *(float4*)&Asb[(j1 >> 4) * AS_STRIDE + (j1 & 15) * 4] = c1;
    if (tid < 32)
        *(float4*)&bsb[tid * 4] = rb;
}

__global__ __launch_bounds__(128) void main_kernel(
    const float* __restrict__ messages,
    const float* __restrict__ tau_values,
    const float* __restrict__ W1,
    const float* __restrict__ W2,
    const float* __restrict__ b2,
    float* __restrict__ out,
    int nGroups)
{
    __shared__ float As[2][16 * AS_STRIDE];
    __shared__ float bsm[2][HIDDEN];
    __shared__ float red[16][4];

    const int tid   = threadIdx.x;
    const int lane  = tid & 31;
    const int w     = tid >> 5;        // warp 0..3, owns cols [w*32, w*32+32)
    const int q     = lane & 3;        // threadID_in_group
    const int gq    = lane >> 2;       // groupID (row within m16 tile)
    const int wbase = w * 32;

    // --- Persistent B fragments: Wm = W1 rows 64..127 (once per CTA) ---
    uint32_t bf[4][8][2];
    const float* Wm = W1 + NODE_DIM * HIDDEN;
    #pragma unroll
    for (int nb = 0; nb < 4; ++nb) {
        const int col = wbase + nb * 8 + gq;
        #pragma unroll
        for (int k = 0; k < 8; ++k) {
            float v0 = Wm[(k * 8 + q) * HIDDEN + col];
            float v1 = Wm[(k * 8 + q + 4) * HIDDEN + col];
            asm("cvt.rna.tf32.f32 %0, %1;" : "=r"(bf[nb][k][0]) : "f"(v0));
            asm("cvt.rna.tf32.f32 %0, %1;" : "=r"(bf[nb][k][1]) : "f"(v1));
        }
    }
    // --- Wt / W2 for this thread's 8 output columns (D-fragment cols) ---
    float wtr[4][2], w2r[4][2];
    #pragma unroll
    for (int nb = 0; nb < 4; ++nb) {
        const int c0 = wbase + nb * 8 + q * 2;
        wtr[nb][0] = W1[(NODE_DIM + MSG_DIM) * HIDDEN + c0];
        wtr[nb][1] = W1[(NODE_DIM + MSG_DIM) * HIDDEN + c0 + 1];
        w2r[nb][0] = W2[c0];
        w2r[nb][1] = W2[c0 + 1];
    }
    const float b2v = b2[0];

    int g = blockIdx.x;
    if (g >= nGroups) return;

    // Prologue: stage first tile
    {
        float4 r0, r1, rb = make_float4(0.f, 0.f, 0.f, 0.f);
        stage_loads(messages, g, tid, r0, r1, rb);
        stage_store(As[0], bsm[0], tid, r0, r1, rb);
    }
    __syncthreads();

    int cur = 0;
    for (;;) {
        const int gn = g + gridDim.x;
        const bool hasNext = (gn < nGroups);

        // Issue next tile's global loads early (registers)
        float4 r0, r1, rb = make_float4(0.f, 0.f, 0.f, 0.f);
        if (hasNext) stage_loads(messages, gn, tid, r0, r1, rb);

        const float tauv = __ldg(&tau_values[g & (T_DIM - 1)]);

        // --- MMA: 16x128 = (16x64) @ (64x128) over 8 K-steps ---
        float acc[4][4];
        #pragma unroll
        for (int nb = 0; nb < 4; ++nb)
            #pragma unroll
            for (int i = 0; i < 4; ++i) acc[nb][i] = 0.f;

        const float* Ab = As[cur];
        #pragma unroll
        for (int k = 0; k < 8; ++k) {
            const float* Ak = Ab + k * 8 + q;
            uint32_t a0 = __float_as_uint(Ak[gq * AS_STRIDE]);
            uint32_t a1 = __float_as_uint(Ak[(gq + 8) * AS_STRIDE]);
            uint32_t a2 = __float_as_uint(Ak[gq * AS_STRIDE + 4]);
            uint32_t a3 = __float_as_uint(Ak[(gq + 8) * AS_STRIDE + 4]);
            #pragma unroll
            for (int nb = 0; nb < 4; ++nb)
                MMA_TF32(acc[nb], a0, a1, a2, a3, bf[nb][k][0], bf[nb][k][1]);
        }

        // --- Epilogue: +base +tau*Wt, relu, *W2, reduce over columns ---
        float ps_lo = 0.f, ps_hi = 0.f;   // rows gq and gq+8
        #pragma unroll
        for (int nb = 0; nb < 4; ++nb) {
            const int c0 = wbase + nb * 8 + q * 2;
            float add0 = fmaf(tauv, wtr[nb][0], bsm[cur][c0]);
            float add1 = fmaf(tauv, wtr[nb][1], bsm[cur][c0 + 1]);
            ps_lo = fmaf(fmaxf(acc[nb][0] + add0, 0.f), w2r[nb][0], ps_lo);
            ps_lo = fmaf(fmaxf(acc[nb][1] + add1, 0.f), w2r[nb][1], ps_lo);
            ps_hi = fmaf(fmaxf(acc[nb][2] + add0, 0.f), w2r[nb][0], ps_hi);
            ps_hi = fmaf(fmaxf(acc[nb][3] + add1, 0.f), w2r[nb][1], ps_hi);
        }
        ps_lo += __shfl_xor_sync(0xffffffffu, ps_lo, 1);
        ps_lo += __shfl_xor_sync(0xffffffffu, ps_lo, 2);
        ps_hi += __shfl_xor_sync(0xffffffffu, ps_hi, 1);
        ps_hi += __shfl_xor_sync(0xffffffffu, ps_hi, 2);
        if (q == 0) {
            red[gq][w]     = ps_lo;
            red[gq + 8][w] = ps_hi;
        }
        __syncthreads();

        if (tid < 16)
            out[(size_t)g * S_DIM + tid] =
                red[tid][0] + red[tid][1] + red[tid][2] + red[tid][3] + b2v;

        if (!hasNext) break;

        stage_store(As[cur ^ 1], bsm[cur ^ 1], tid, r0, r1, rb);
        __syncthreads();
        cur ^= 1;
        g = gn;
    }
}

// ---------------------------------------------------------------------------
extern "C" void kernel_launch(void* const* d_in, const int* in_sizes, int n_in,
                              void* d_out, int out_size)
{
    const float* h_t      = (const float*)d_in[0];
    const float* messages = (const float*)d_in[1];
    const float* tau      = (const float*)d_in[2];
    const float* theta    = (const float*)d_in[3];
    const float* W1       = (const float*)d_in[4];
    const float* b1       = (const float*)d_in[5];
    const float* W2       = (const float*)d_in[6];
    const float* b2       = (const float*)d_in[7];
    float* out = (float*)d_out;

    const int V = in_sizes[0] / NODE_DIM;
    const int nGroups = V * T_DIM;

    const int smem1 = (96 * 128 + 128 + 16 * 96) * (int)sizeof(float);  // 55808 B
    cudaFuncSetAttribute(base_kernel,
                         cudaFuncAttributeMaxDynamicSharedMemorySize, smem1);

    base_kernel<<<(V + 63) / 64, 256, smem1>>>(h_t, theta, W1, b1, V);

    int grid = 1184;
    if (grid > nGroups) grid = nGroups;
    main_kernel<<<grid, 128>>>(messages, tau, W1, W2, b2, out, nGroups);
}

// round 2
// speedup vs baseline: 1.2539x; 1.2539x over previous
#include <cuda_runtime.h>
#include <cstdint>

#define NODE_DIM 64
#define MSG_DIM  64
#define PROP_DIM 32
#define HIDDEN   128
#define T_DIM    8
#define S_DIM    16

#define MAX_V    10000
#define AS_STRIDE 68   // 64 + 4 pad: conflict-free mma A-fragment LDS
#define GQ 4           // groups per CTA iteration (one quad = one node's 4 t-slices)

// Scratch: base[v][h] = h_t[v].Wh + theta[v].Wp + b1
__device__ float g_base[MAX_V * HIDDEN];

#define MMA_TF32(D, a0, a1, a2, a3, b0, b1)                                   \
    asm volatile(                                                             \
        "mma.sync.aligned.m16n8k8.row.col.f32.tf32.tf32.f32 "                 \
        "{%0,%1,%2,%3}, {%4,%5,%6,%7}, {%8,%9}, {%0,%1,%2,%3};"               \
        : "+f"(D[0]), "+f"(D[1]), "+f"(D[2]), "+f"(D[3])                      \
        : "r"(a0), "r"(a1), "r"(a2), "r"(a3), "r"(b0), "r"(b1))

__device__ __forceinline__ void cp_async16(uint32_t dst_smem, const void* src) {
    asm volatile("cp.async.cg.shared.global [%0], [%1], 16;" :: "r"(dst_smem), "l"(src));
}

// ---------------------------------------------------------------------------
// Kernel 1: base[v][h] (fp32 FMA, ~8us)
// W1 rows: Wh = 0..63, Wm = 64..127, Wt = 128, Wp = 129..160
// ---------------------------------------------------------------------------
__global__ __launch_bounds__(256) void base_kernel(
    const float* __restrict__ h_t,
    const float* __restrict__ theta,
    const float* __restrict__ W1,
    const float* __restrict__ b1,
    int V)
{
    extern __shared__ float sm1[];
    float* Wsm  = sm1;               // 96*128
    float* b1sm = sm1 + 96 * 128;    // 128
    float* hsm  = b1sm + 128;        // 16*96

    const int tid = threadIdx.x;

    for (int i = tid; i < 96 * 128; i += 256) {
        int r = i >> 7;
        int c = i & 127;
        int gr = (r < NODE_DIM) ? r : (NODE_DIM + MSG_DIM + 1 + (r - NODE_DIM));
        Wsm[i] = W1[gr * HIDDEN + c];
    }
    if (tid < HIDDEN) b1sm[tid] = b1[tid];

    const int v0 = blockIdx.x * 64;

    for (int pass = 0; pass < 4; ++pass) {
        __syncthreads();
        const int vp = v0 + pass * 16;

        for (int i = tid; i < 16 * 64; i += 256) {
            int v = i >> 6, d = i & 63;
            hsm[v * 96 + d] = (vp + v < V) ? h_t[(size_t)(vp + v) * NODE_DIM + d] : 0.f;
        }
        for (int i = tid; i < 16 * 32; i += 256) {
            int v = i >> 5, p = i & 31;
            hsm[v * 96 + 64 + p] = (vp + v < V) ? theta[(size_t)(vp + v) * PROP_DIM + p] : 0.f;
        }
        __syncthreads();

        const int h4 = (tid & 31) * 4;
        const int vl = (tid >> 5) * 2;

        float4 acc0 = *(const float4*)&b1sm[h4];
        float4 acc1 = acc0;
        const float* hv0 = &hsm[vl * 96];
        const float* hv1 = hv0 + 96;

        #pragma unroll 8
        for (int d = 0; d < 96; ++d) {
            float4 ww = *(const float4*)&Wsm[d * 128 + h4];
            float x0 = hv0[d], x1 = hv1[d];
            acc0.x = fmaf(x0, ww.x, acc0.x);
            acc0.y = fmaf(x0, ww.y, acc0.y);
            acc0.z = fmaf(x0, ww.z, acc0.z);
            acc0.w = fmaf(x0, ww.w, acc0.w);
            acc1.x = fmaf(x1, ww.x, acc1.x);
            acc1.y = fmaf(x1, ww.y, acc1.y);
            acc1.z = fmaf(x1, ww.z, acc1.z);
            acc1.w = fmaf(x1, ww.w, acc1.w);
        }
        if (vp + vl < V)
            *(float4*)&g_base[(size_t)(vp + vl) * HIDDEN + h4] = acc0;
        if (vp + vl + 1 < V)
            *(float4*)&g_base[(size_t)(vp + vl + 1) * HIDDEN + h4] = acc1;
    }
}

// ---------------------------------------------------------------------------
// Kernel 2: quad-tile main GEMM + fused epilogue.
// Each CTA iteration: 4 consecutive groups (same node v), 64 rows x 128 cols.
// Messages + base staged via cp.async (double buffered). tf32 cvt at use.
// ---------------------------------------------------------------------------

__device__ __forceinline__ void stage_quad(
    float* Asb, float* bsb,
    const float* __restrict__ messages, int q, int tid)
{
    const float* msrc = messages + (size_t)q * (GQ * S_DIM * MSG_DIM);
    #pragma unroll
    for (int i = 0; i < 8; ++i) {
        int c   = tid + i * 128;      // 16B chunk index, 0..1023
        int grp = c >> 8;
        int m   = c & 255;
        int row = m >> 4;
        int cc  = m & 15;
        uint32_t dst = (uint32_t)__cvta_generic_to_shared(
            Asb + grp * (S_DIM * AS_STRIDE) + row * AS_STRIDE + cc * 4);
        cp_async16(dst, msrc + c * 4);
    }
    if (tid < 32) {
        int v = q >> 1;   // quad q covers groups 4q..4q+3, node = 4q/8 = q/2
        uint32_t dst = (uint32_t)__cvta_generic_to_shared(bsb + tid * 4);
        cp_async16(dst, g_base + (size_t)v * HIDDEN + tid * 4);
    }
}

__global__ __launch_bounds__(128, 3) void main_kernel(
    const float* __restrict__ messages,
    const float* __restrict__ tau_values,
    const float* __restrict__ W1,
    const float* __restrict__ W2,
    const float* __restrict__ b2,
    float* __restrict__ out,
    int nGroups, int nQuads)
{
    __shared__ float As[2][GQ * S_DIM * AS_STRIDE];  // 2 x 4352 floats
    __shared__ float bsm[2][HIDDEN];
    __shared__ float red[GQ][S_DIM][4];
    __shared__ float tau_sm[T_DIM];

    const int tid   = threadIdx.x;
    const int lane  = tid & 31;
    const int w     = tid >> 5;        // warp owns cols [w*32, w*32+32)
    const int qd    = lane & 3;        // thread-in-group
    const int gq    = lane >> 2;       // row within m16 tile
    const int wbase = w * 32;

    // --- Persistent B fragments: Wm = W1 rows 64..127 (tf32-rna) ---
    uint32_t bf[4][8][2];
    const float* Wm = W1 + NODE_DIM * HIDDEN;
    #pragma unroll
    for (int nb = 0; nb < 4; ++nb) {
        const int col = wbase + nb * 8 + gq;
        #pragma unroll
        for (int k = 0; k < 8; ++k) {
            float v0 = Wm[(k * 8 + qd) * HIDDEN + col];
            float v1 = Wm[(k * 8 + qd + 4) * HIDDEN + col];
            asm("cvt.rna.tf32.f32 %0, %1;" : "=r"(bf[nb][k][0]) : "f"(v0));
            asm("cvt.rna.tf32.f32 %0, %1;" : "=r"(bf[nb][k][1]) : "f"(v1));
        }
    }
    // --- Wt / W2 per-thread column constants ---
    float wtr[4][2], w2r[4][2];
    #pragma unroll
    for (int nb = 0; nb < 4; ++nb) {
        const int c0 = wbase + nb * 8 + qd * 2;
        wtr[nb][0] = W1[(NODE_DIM + MSG_DIM) * HIDDEN + c0];
        wtr[nb][1] = W1[(NODE_DIM + MSG_DIM) * HIDDEN + c0 + 1];
        w2r[nb][0] = W2[c0];
        w2r[nb][1] = W2[c0 + 1];
    }
    const float b2v = __ldg(&b2[0]);

    if (tid < T_DIM) tau_sm[tid] = tau_values[tid];

    int q = blockIdx.x;   // grid clamped to nQuads: always valid

    stage_quad(As[0], bsm[0], messages, q, tid);
    asm volatile("cp.async.commit_group;");

    int cur = 0;
    for (;;) {
        const int qn = q + gridDim.x;
        const bool hasNext = (qn < nQuads);

        if (hasNext) {
            stage_quad(As[cur ^ 1], bsm[cur ^ 1], messages, qn, tid);
            asm volatile("cp.async.commit_group;");
            asm volatile("cp.async.wait_group 1;");
        } else {
            asm volatile("cp.async.wait_group 0;");
        }
        __syncthreads();   // buf[cur] (+ tau_sm on first pass) visible

        const int g0 = q * GQ;
        const int t0 = g0 & (T_DIM - 1);
        const float* bcur = bsm[cur];

        #pragma unroll 2
        for (int j = 0; j < GQ; ++j) {
            const float* Ab = &As[cur][j * (S_DIM * AS_STRIDE)];

            float acc[4][4];
            #pragma unroll
            for (int nb = 0; nb < 4; ++nb)
                #pragma unroll
                for (int i = 0; i < 4; ++i) acc[nb][i] = 0.f;

            #pragma unroll
            for (int k = 0; k < 8; ++k) {
                const float* Ak = Ab + k * 8 + qd;
                uint32_t a0, a1, a2, a3;
                asm("cvt.rna.tf32.f32 %0, %1;" : "=r"(a0) : "f"(Ak[gq * AS_STRIDE]));
                asm("cvt.rna.tf32.f32 %0, %1;" : "=r"(a1) : "f"(Ak[(gq + 8) * AS_STRIDE]));
                asm("cvt.rna.tf32.f32 %0, %1;" : "=r"(a2) : "f"(Ak[gq * AS_STRIDE + 4]));
                asm("cvt.rna.tf32.f32 %0, %1;" : "=r"(a3) : "f"(Ak[(gq + 8) * AS_STRIDE + 4]));
                #pragma unroll
                for (int nb = 0; nb < 4; ++nb)
                    MMA_TF32(acc[nb], a0, a1, a2, a3, bf[nb][k][0], bf[nb][k][1]);
            }

            // Epilogue: +base +tau*Wt, relu, *W2, column reduce
            const float tauv = tau_sm[t0 + j];
            float ps_lo = 0.f, ps_hi = 0.f;
            #pragma unroll
            for (int nb = 0; nb < 4; ++nb) {
                const int c0 = wbase + nb * 8 + qd * 2;
                float add0 = fmaf(tauv, wtr[nb][0], bcur[c0]);
                float add1 = fmaf(tauv, wtr[nb][1], bcur[c0 + 1]);
                ps_lo = fmaf(fmaxf(acc[nb][0] + add0, 0.f), w2r[nb][0], ps_lo);
                ps_lo = fmaf(fmaxf(acc[nb][1] + add1, 0.f), w2r[nb][1], ps_lo);
                ps_hi = fmaf(fmaxf(acc[nb][2] + add0, 0.f), w2r[nb][0], ps_hi);
                ps_hi = fmaf(fmaxf(acc[nb][3] + add1, 0.f), w2r[nb][1], ps_hi);
            }
            ps_lo += __shfl_xor_sync(0xffffffffu, ps_lo, 1);
            ps_lo += __shfl_xor_sync(0xffffffffu, ps_lo, 2);
            ps_hi += __shfl_xor_sync(0xffffffffu, ps_hi, 1);
            ps_hi += __shfl_xor_sync(0xffffffffu, ps_hi, 2);
            if (qd == 0) {
                red[j][gq][w]     = ps_lo;
                red[j][gq + 8][w] = ps_hi;
            }
        }
        __syncthreads();   // red ready + buf[cur] fully consumed

        if (tid < GQ * S_DIM) {
            const int j   = tid >> 4;
            const int row = tid & 15;
            const int g   = g0 + j;
            if (g < nGroups)
                out[(size_t)g * S_DIM + row] =
                    red[j][row][0] + red[j][row][1] +
                    red[j][row][2] + red[j][row][3] + b2v;
        }

        if (!hasNext) break;
        cur ^= 1;
        q = qn;
    }
}

// ---------------------------------------------------------------------------
extern "C" void kernel_launch(void* const* d_in, const int* in_sizes, int n_in,
                              void* d_out, int out_size)
{
    const float* h_t      = (const float*)d_in[0];
    const float* messages = (const float*)d_in[1];
    const float* tau      = (const float*)d_in[2];
    const float* theta    = (const float*)d_in[3];
    const float* W1       = (const float*)d_in[4];
    const float* b1       = (const float*)d_in[5];
    const float* W2       = (const float*)d_in[6];
    const float* b2       = (const float*)d_in[7];
    float* out = (float*)d_out;

    const int V = in_sizes[0] / NODE_DIM;
    const int nGroups = V * T_DIM;
    const int nQuads  = nGroups / GQ;   // T=8 -> divisible by 4

    const int smem1 = (96 * 128 + 128 + 16 * 96) * (int)sizeof(float);
    cudaFuncSetAttribute(base_kernel,
                         cudaFuncAttributeMaxDynamicSharedMemorySize, smem1);

    base_kernel<<<(V + 63) / 64, 256, smem1>>>(h_t, theta, W1, b1, V);

    int grid = 1184;
    if (grid > nQuads) grid = nQuads;
    main_kernel<<<grid, 128>>>(messages, tau, W1, W2, b2, out, nGroups, nQuads);
}

// round 3
// speedup vs baseline: 1.2839x; 1.0239x over previous
#include <cuda_runtime.h>
#include <cstdint>

#define NODE_DIM 64
#define MSG_DIM  64
#define PROP_DIM 32
#define HIDDEN   128
#define T_DIM    8
#define S_DIM    16

#define MAX_V    10000
#define AS_STRIDE 68   // 64 + 4 pad: conflict-free mma A-fragment LDS
#define GQ 4           // groups per CTA iteration (one quad = one node's 4 t-slices)

// Scratch: base[v][h] = h_t[v].Wh + theta[v].Wp + b1
__device__ float g_base[MAX_V * HIDDEN];

#define MMA_TF32(D, a0, a1, a2, a3, b0, b1)                                   \
    asm volatile(                                                             \
        "mma.sync.aligned.m16n8k8.row.col.f32.tf32.tf32.f32 "                 \
        "{%0,%1,%2,%3}, {%4,%5,%6,%7}, {%8,%9}, {%0,%1,%2,%3};"               \
        : "+f"(D[0]), "+f"(D[1]), "+f"(D[2]), "+f"(D[3])                      \
        : "r"(a0), "r"(a1), "r"(a2), "r"(a3), "r"(b0), "r"(b1))

__device__ __forceinline__ void cp_async16(uint32_t dst_smem, const void* src) {
    asm volatile("cp.async.cg.shared.global [%0], [%1], 16;" :: "r"(dst_smem), "l"(src));
}

// ---------------------------------------------------------------------------
// Kernel 1: base[v][h] (fp32 FMA)
// W1 rows: Wh = 0..63, Wm = 64..127, Wt = 128, Wp = 129..160
// ---------------------------------------------------------------------------
__global__ __launch_bounds__(256) void base_kernel(
    const float* __restrict__ h_t,
    const float* __restrict__ theta,
    const float* __restrict__ W1,
    const float* __restrict__ b1,
    int V)
{
    extern __shared__ float sm1[];
    float* Wsm  = sm1;               // 96*128
    float* b1sm = sm1 + 96 * 128;    // 128
    float* hsm  = b1sm + 128;        // 16*96

    const int tid = threadIdx.x;

    for (int i = tid; i < 96 * 128; i += 256) {
        int r = i >> 7;
        int c = i & 127;
        int gr = (r < NODE_DIM) ? r : (NODE_DIM + MSG_DIM + 1 + (r - NODE_DIM));
        Wsm[i] = W1[gr * HIDDEN + c];
    }
    if (tid < HIDDEN) b1sm[tid] = b1[tid];

    const int v0 = blockIdx.x * 64;

    for (int pass = 0; pass < 4; ++pass) {
        __syncthreads();
        const int vp = v0 + pass * 16;

        for (int i = tid; i < 16 * 64; i += 256) {
            int v = i >> 6, d = i & 63;
            hsm[v * 96 + d] = (vp + v < V) ? h_t[(size_t)(vp + v) * NODE_DIM + d] : 0.f;
        }
        for (int i = tid; i < 16 * 32; i += 256) {
            int v = i >> 5, p = i & 31;
            hsm[v * 96 + 64 + p] = (vp + v < V) ? theta[(size_t)(vp + v) * PROP_DIM + p] : 0.f;
        }
        __syncthreads();

        const int h4 = (tid & 31) * 4;
        const int vl = (tid >> 5) * 2;

        float4 acc0 = *(const float4*)&b1sm[h4];
        float4 acc1 = acc0;
        const float* hv0 = &hsm[vl * 96];
        const float* hv1 = hv0 + 96;

        #pragma unroll 8
        for (int d = 0; d < 96; ++d) {
            float4 ww = *(const float4*)&Wsm[d * 128 + h4];
            float x0 = hv0[d], x1 = hv1[d];
            acc0.x = fmaf(x0, ww.x, acc0.x);
            acc0.y = fmaf(x0, ww.y, acc0.y);
            acc0.z = fmaf(x0, ww.z, acc0.z);
            acc0.w = fmaf(x0, ww.w, acc0.w);
            acc1.x = fmaf(x1, ww.x, acc1.x);
            acc1.y = fmaf(x1, ww.y, acc1.y);
            acc1.z = fmaf(x1, ww.z, acc1.z);
            acc1.w = fmaf(x1, ww.w, acc1.w);
        }
        if (vp + vl < V)
            *(float4*)&g_base[(size_t)(vp + vl) * HIDDEN + h4] = acc0;
        if (vp + vl + 1 < V)
            *(float4*)&g_base[(size_t)(vp + vl + 1) * HIDDEN + h4] = acc1;
    }
}

// ---------------------------------------------------------------------------
// Kernel 2: quad-tile main GEMM + fused epilogue, 4 CTAs/SM target.
// ---------------------------------------------------------------------------

__device__ __forceinline__ void stage_quad(
    float* Asb, float* bsb,
    const float* __restrict__ messages, int q, int tid)
{
    const float* msrc = messages + (size_t)q * (GQ * S_DIM * MSG_DIM);
    #pragma unroll
    for (int i = 0; i < 8; ++i) {
        int c   = tid + i * 128;      // 16B chunk index, 0..1023
        int grp = c >> 8;
        int m   = c & 255;
        int row = m >> 4;
        int cc  = m & 15;
        uint32_t dst = (uint32_t)__cvta_generic_to_shared(
            Asb + grp * (S_DIM * AS_STRIDE) + row * AS_STRIDE + cc * 4);
        cp_async16(dst, msrc + c * 4);
    }
    if (tid < 32) {
        int v = q >> 1;   // quad q covers groups 4q..4q+3 -> node = q/2
        uint32_t dst = (uint32_t)__cvta_generic_to_shared(bsb + tid * 4);
        cp_async16(dst, g_base + (size_t)v * HIDDEN + tid * 4);
    }
}

__global__ __launch_bounds__(128, 4) void main_kernel(
    const float* __restrict__ messages,
    const float* __restrict__ tau_values,
    const float* __restrict__ W1,
    const float* __restrict__ W2,
    const float* __restrict__ b2,
    float* __restrict__ out,
    int nGroups, int nQuads)
{
    __shared__ float As[2][GQ * S_DIM * AS_STRIDE];  // 34816 B
    __shared__ float bsm[2][HIDDEN];                 // 1024 B
    __shared__ float red[GQ][S_DIM][4];              // 1024 B
    __shared__ float taW[T_DIM][HIDDEN];             // 4096 B: tau_t * Wt[c]
    __shared__ float W2sm[HIDDEN];                   // 512 B

    const int tid   = threadIdx.x;
    const int lane  = tid & 31;
    const int w     = tid >> 5;        // warp owns cols [w*32, w*32+32)
    const int qd    = lane & 3;        // thread-in-group
    const int gq    = lane >> 2;       // row within m16 tile
    const int wbase = w * 32;

    int q = blockIdx.x;   // grid clamped to nQuads

    // Kick off the first stage ASAP so cp.async overlaps prologue setup.
    stage_quad(As[0], bsm[0], messages, q, tid);
    asm volatile("cp.async.commit_group;");

    // --- Persistent B fragments: Wm = W1 rows 64..127 (tf32-rna), 64 regs ---
    uint32_t bf[4][8][2];
    const float* Wm = W1 + NODE_DIM * HIDDEN;
    #pragma unroll
    for (int nb = 0; nb < 4; ++nb) {
        const int col = wbase + nb * 8 + gq;
        #pragma unroll
        for (int k = 0; k < 8; ++k) {
            float v0 = Wm[(k * 8 + qd) * HIDDEN + col];
            float v1 = Wm[(k * 8 + qd + 4) * HIDDEN + col];
            asm("cvt.rna.tf32.f32 %0, %1;" : "=r"(bf[nb][k][0]) : "f"(v0));
            asm("cvt.rna.tf32.f32 %0, %1;" : "=r"(bf[nb][k][1]) : "f"(v1));
        }
    }

    // --- Epilogue constants in smem (no persistent regs) ---
    {
        const float* Wt = W1 + (NODE_DIM + MSG_DIM) * HIDDEN;
        float wt = Wt[tid];
        #pragma unroll
        for (int t = 0; t < T_DIM; ++t)
            taW[t][tid] = __ldg(&tau_values[t]) * wt;
        W2sm[tid] = W2[tid];
    }
    const float b2v = __ldg(&b2[0]);

    int cur = 0;
    for (;;) {
        const int qn = q + gridDim.x;
        const bool hasNext = (qn < nQuads);

        if (hasNext) {
            stage_quad(As[cur ^ 1], bsm[cur ^ 1], messages, qn, tid);
            asm volatile("cp.async.commit_group;");
            asm volatile("cp.async.wait_group 1;");
        } else {
            asm volatile("cp.async.wait_group 0;");
        }
        __syncthreads();   // buf[cur] (+ taW/W2sm on first pass) visible

        const int g0 = q * GQ;
        const int t0 = g0 & (T_DIM - 1);
        const float* bcur = bsm[cur];

        #pragma unroll 2
        for (int j = 0; j < GQ; ++j) {
            const float* Ab = &As[cur][j * (S_DIM * AS_STRIDE)];

            float acc[4][4];
            #pragma unroll
            for (int nb = 0; nb < 4; ++nb)
                #pragma unroll
                for (int i = 0; i < 4; ++i) acc[nb][i] = 0.f;

            #pragma unroll
            for (int k = 0; k < 8; ++k) {
                const float* Ak = Ab + k * 8 + qd;
                uint32_t a0, a1, a2, a3;
                asm("cvt.rna.tf32.f32 %0, %1;" : "=r"(a0) : "f"(Ak[gq * AS_STRIDE]));
                asm("cvt.rna.tf32.f32 %0, %1;" : "=r"(a1) : "f"(Ak[(gq + 8) * AS_STRIDE]));
                asm("cvt.rna.tf32.f32 %0, %1;" : "=r"(a2) : "f"(Ak[gq * AS_STRIDE + 4]));
                asm("cvt.rna.tf32.f32 %0, %1;" : "=r"(a3) : "f"(Ak[(gq + 8) * AS_STRIDE + 4]));
                #pragma unroll
                for (int nb = 0; nb < 4; ++nb)
                    MMA_TF32(acc[nb], a0, a1, a2, a3, bf[nb][k][0], bf[nb][k][1]);
            }

            // Epilogue: +base +tau*Wt (precomputed), relu, *W2, column reduce
            const float* taWj = taW[t0 + j];
            float ps_lo = 0.f, ps_hi = 0.f;
            #pragma unroll
            for (int nb = 0; nb < 4; ++nb) {
                const int c0 = wbase + nb * 8 + qd * 2;
                float2 bb = *(const float2*)&bcur[c0];
                float2 tw = *(const float2*)&taWj[c0];
                float2 w2 = *(const float2*)&W2sm[c0];
                float add0 = bb.x + tw.x;
                float add1 = bb.y + tw.y;
                ps_lo = fmaf(fmaxf(acc[nb][0] + add0, 0.f), w2.x, ps_lo);
                ps_lo = fmaf(fmaxf(acc[nb][1] + add1, 0.f), w2.y, ps_lo);
                ps_hi = fmaf(fmaxf(acc[nb][2] + add0, 0.f), w2.x, ps_hi);
                ps_hi = fmaf(fmaxf(acc[nb][3] + add1, 0.f), w2.y, ps_hi);
            }
            ps_lo += __shfl_xor_sync(0xffffffffu, ps_lo, 1);
            ps_lo += __shfl_xor_sync(0xffffffffu, ps_lo, 2);
            ps_hi += __shfl_xor_sync(0xffffffffu, ps_hi, 1);
            ps_hi += __shfl_xor_sync(0xffffffffu, ps_hi, 2);
            if (qd == 0) {
                red[j][gq][w]     = ps_lo;
                red[j][gq + 8][w] = ps_hi;
            }
        }
        __syncthreads();   // red ready + buf[cur] fully consumed

        if (tid < GQ * S_DIM) {
            const int j   = tid >> 4;
            const int row = tid & 15;
            const int g   = g0 + j;
            if (g < nGroups)
                out[(size_t)g * S_DIM + row] =
                    red[j][row][0] + red[j][row][1] +
                    red[j][row][2] + red[j][row][3] + b2v;
        }

        if (!hasNext) break;
        cur ^= 1;
        q = qn;
    }
}

// ---------------------------------------------------------------------------
extern "C" void kernel_launch(void* const* d_in, const int* in_sizes, int n_in,
                              void* d_out, int out_size)
{
    const float* h_t      = (const float*)d_in[0];
    const float* messages = (const float*)d_in[1];
    const float* tau      = (const float*)d_in[2];
    const float* theta    = (const float*)d_in[3];
    const float* W1       = (const float*)d_in[4];
    const float* b1       = (const float*)d_in[5];
    const float* W2       = (const float*)d_in[6];
    const float* b2       = (const float*)d_in[7];
    float* out = (float*)d_out;

    const int V = in_sizes[0] / NODE_DIM;
    const int nGroups = V * T_DIM;
    const int nQuads  = nGroups / GQ;

    const int smem1 = (96 * 128 + 128 + 16 * 96) * (int)sizeof(float);
    cudaFuncSetAttribute(base_kernel,
                         cudaFuncAttributeMaxDynamicSharedMemorySize, smem1);

    base_kernel<<<(V + 63) / 64, 256, smem1>>>(h_t, theta, W1, b1, V);

    // Grid = exactly the resident CTA count (persistent style, no waves).
    int nb_occ = 0, nsm = 148;
    cudaOccupancyMaxActiveBlocksPerMultiprocessor(&nb_occ, main_kernel, 128, 0);
    cudaDeviceGetAttribute(&nsm, cudaDevAttrMultiProcessorCount, 0);
    if (nb_occ < 1) nb_occ = 3;
    int grid = nb_occ * nsm;
    if (grid > nQuads) grid = nQuads;

    main_kernel<<<grid, 128>>>(messages, tau, W1, W2, b2, out, nGroups, nQuads);
}

// round 5
// speedup vs baseline: 1.8277x; 1.4236x over previous
#include <cuda_runtime.h>
#include <cstdint>

#define NODE_DIM 64
#define MSG_DIM  64
#define PROP_DIM 32
#define HIDDEN   128
#define T_DIM    8
#define S_DIM    16

#define MAX_V    10000
#define FSTR 72        // floats per A row in smem (64 + 8 pad): conflict-free LDS.64
#define GROUP_FLOATS (S_DIM * FSTR)   // 1152
#define GQ 4           // groups per CTA iteration

// Scratch: base[v][h] = h_t[v].Wh + theta[v].Wp + b1
__device__ float g_base[MAX_V * HIDDEN];

// pack two fp32 -> fp16x2 (lo = first arg), round-to-nearest-even
__device__ __forceinline__ uint32_t pack_h2(float lo, float hi) {
    uint32_t r;
    asm("cvt.rn.f16x2.f32 %0, %1, %2;" : "=r"(r) : "f"(hi), "f"(lo));
    return r;
}

#define MMA_F16(D, a0, a1, a2, a3, b0, b1)                                    \
    asm volatile(                                                             \
        "mma.sync.aligned.m16n8k16.row.col.f32.f16.f16.f32 "                  \
        "{%0,%1,%2,%3}, {%4,%5,%6,%7}, {%8,%9}, {%0,%1,%2,%3};"               \
        : "+f"(D[0]), "+f"(D[1]), "+f"(D[2]), "+f"(D[3])                      \
        : "r"(a0), "r"(a1), "r"(a2), "r"(a3), "r"(b0), "r"(b1))

__device__ __forceinline__ void cp_async16(uint32_t dst_smem, const void* src) {
    asm volatile("cp.async.cg.shared.global [%0], [%1], 16;" :: "r"(dst_smem), "l"(src));
}

// ---------------------------------------------------------------------------
// Kernel 1: base[v][h].  16 nodes per CTA (full-chip wave), single pass.
// W1 rows: Wh = 0..63, Wm = 64..127, Wt = 128, Wp = 129..160
// ---------------------------------------------------------------------------
__global__ __launch_bounds__(256) void base_kernel(
    const float* __restrict__ h_t,
    const float* __restrict__ theta,
    const float* __restrict__ W1,
    const float* __restrict__ b1,
    int V)
{
    extern __shared__ float sm1[];
    float* Wsm  = sm1;               // 96*128
    float* b1sm = sm1 + 96 * 128;    // 128
    float* hsm  = b1sm + 128;        // 16*96

    const int tid = threadIdx.x;

    for (int i = tid; i < 96 * 128; i += 256) {
        int r = i >> 7;
        int c = i & 127;
        int gr = (r < NODE_DIM) ? r : (NODE_DIM + MSG_DIM + 1 + (r - NODE_DIM));
        Wsm[i] = W1[gr * HIDDEN + c];
    }
    if (tid < HIDDEN) b1sm[tid] = b1[tid];

    const int vp = blockIdx.x * 16;

    for (int i = tid; i < 16 * 64; i += 256) {
        int v = i >> 6, d = i & 63;
        hsm[v * 96 + d] = (vp + v < V) ? h_t[(size_t)(vp + v) * NODE_DIM + d] : 0.f;
    }
    for (int i = tid; i < 16 * 32; i += 256) {
        int v = i >> 5, p = i & 31;
        hsm[v * 96 + 64 + p] = (vp + v < V) ? theta[(size_t)(vp + v) * PROP_DIM + p] : 0.f;
    }
    __syncthreads();

    const int h4 = (tid & 31) * 4;
    const int vl = (tid >> 5) * 2;

    float4 acc0 = *(const float4*)&b1sm[h4];
    float4 acc1 = acc0;
    const float* hv0 = &hsm[vl * 96];
    const float* hv1 = hv0 + 96;

    #pragma unroll 8
    for (int d = 0; d < 96; ++d) {
        float4 ww = *(const float4*)&Wsm[d * 128 + h4];
        float x0 = hv0[d], x1 = hv1[d];
        acc0.x = fmaf(x0, ww.x, acc0.x);
        acc0.y = fmaf(x0, ww.y, acc0.y);
        acc0.z = fmaf(x0, ww.z, acc0.z);
        acc0.w = fmaf(x0, ww.w, acc0.w);
        acc1.x = fmaf(x1, ww.x, acc1.x);
        acc1.y = fmaf(x1, ww.y, acc1.y);
        acc1.z = fmaf(x1, ww.z, acc1.z);
        acc1.w = fmaf(x1, ww.w, acc1.w);
    }
    if (vp + vl < V)
        *(float4*)&g_base[(size_t)(vp + vl) * HIDDEN + h4] = acc0;
    if (vp + vl + 1 < V)
        *(float4*)&g_base[(size_t)(vp + vl + 1) * HIDDEN + h4] = acc1;
}

// ---------------------------------------------------------------------------
// Kernel 2: quad-tile fp16 mma.m16n8k16 GEMM + fused epilogue, 5 CTAs/SM.
// A (messages) staged raw-fp32 via cp.async; converted to fp16x2 at use.
// B (Wm, fp16x2, rn) persistent in 32 regs/warp.
// ---------------------------------------------------------------------------

__device__ __forceinline__ void stage_quad(
    float* Asb, float* bsb,
    const float* __restrict__ messages, int q, int tid)
{
    const float* msrc = messages + (size_t)q * (GQ * S_DIM * MSG_DIM);
    #pragma unroll
    for (int i = 0; i < 8; ++i) {
        int c   = tid + i * 128;      // 16B chunk index, 0..1023
        int grp = c >> 8;
        int m   = c & 255;
        int row = m >> 4;
        int cc  = m & 15;
        uint32_t dst = (uint32_t)__cvta_generic_to_shared(
            Asb + grp * GROUP_FLOATS + row * FSTR + cc * 4);
        cp_async16(dst, msrc + c * 4);
    }
    if (tid < 32) {
        int v = q >> 1;   // quad q covers groups 4q..4q+3 -> node = q/2
        uint32_t dst = (uint32_t)__cvta_generic_to_shared(bsb + tid * 4);
        cp_async16(dst, g_base + (size_t)v * HIDDEN + tid * 4);
    }
}

__global__ __launch_bounds__(128, 5) void main_kernel(
    const float* __restrict__ messages,
    const float* __restrict__ tau_values,
    const float* __restrict__ W1,
    const float* __restrict__ W2,
    const float* __restrict__ b2,
    float* __restrict__ out,
    int nGroups, int nQuads)
{
    __shared__ float As[2][GQ * GROUP_FLOATS];       // 36864 B
    __shared__ float bsm[2][HIDDEN];                 // 1024 B
    __shared__ float red[GQ][S_DIM][4];              // 1024 B
    __shared__ float taW[T_DIM][HIDDEN];             // 4096 B
    __shared__ float W2sm[HIDDEN];                   // 512 B

    const int tid   = threadIdx.x;
    const int lane  = tid & 31;
    const int w     = tid >> 5;        // warp owns cols [w*32, w*32+32)
    const int qd    = lane & 3;        // thread-in-group
    const int gq    = lane >> 2;       // row within m16 tile
    const int wbase = w * 32;

    int q = blockIdx.x;   // grid clamped to nQuads

    stage_quad(As[0], bsm[0], messages, q, tid);
    asm volatile("cp.async.commit_group;");

    // --- Persistent B fragments (fp16x2): Wm = W1 rows 64..127, 32 regs ---
    // m16n8k16 B layout: b0 = {B[kk*16+2q][col], B[kk*16+2q+1][col]},
    //                    b1 = {B[kk*16+2q+8][col], B[kk*16+2q+9][col]}
    uint32_t bf[4][4][2];
    {
        const float* Wm = W1 + NODE_DIM * HIDDEN;
        #pragma unroll
        for (int nb = 0; nb < 4; ++nb) {
            const int col = wbase + nb * 8 + gq;
            #pragma unroll
            for (int kk = 0; kk < 4; ++kk) {
                const int kb = kk * 16 + 2 * qd;
                bf[nb][kk][0] = pack_h2(Wm[(kb)     * HIDDEN + col],
                                        Wm[(kb + 1) * HIDDEN + col]);
                bf[nb][kk][1] = pack_h2(Wm[(kb + 8) * HIDDEN + col],
                                        Wm[(kb + 9) * HIDDEN + col]);
            }
        }
    }

    // --- Epilogue constants in smem ---
    {
        const float* Wt = W1 + (NODE_DIM + MSG_DIM) * HIDDEN;
        float wt = Wt[tid];
        #pragma unroll
        for (int t = 0; t < T_DIM; ++t)
            taW[t][tid] = __ldg(&tau_values[t]) * wt;
        W2sm[tid] = W2[tid];
    }
    const float b2v = __ldg(&b2[0]);

    int cur = 0;
    for (;;) {
        const int qn = q + gridDim.x;
        const bool hasNext = (qn < nQuads);

        if (hasNext) {
            stage_quad(As[cur ^ 1], bsm[cur ^ 1], messages, qn, tid);
            asm volatile("cp.async.commit_group;");
            asm volatile("cp.async.wait_group 1;");
        } else {
            asm volatile("cp.async.wait_group 0;");
        }
        __syncthreads();   // buf[cur] (+ taW/W2sm on first pass) visible

        const int g0 = q * GQ;
        const int t0 = g0 & (T_DIM - 1);
        const float* bcur = bsm[cur];

        #pragma unroll 2
        for (int j = 0; j < GQ; ++j) {
            const float* Ab = &As[cur][j * GROUP_FLOATS];

            float acc[4][4];
            #pragma unroll
            for (int nb = 0; nb < 4; ++nb)
                #pragma unroll
                for (int i = 0; i < 4; ++i) acc[nb][i] = 0.f;

            // m16n8k16 A frags: a0={A[gq][kb],A[gq][kb+1]}, a1=rows gq+8,
            //                   a2/a3 = cols +8.  kb = kk*16 + 2q.
            #pragma unroll
            for (int kk = 0; kk < 4; ++kk) {
                const float* Ak = Ab + kk * 16 + 2 * qd;
                float2 v0 = *(const float2*)&Ak[gq * FSTR];
                float2 v1 = *(const float2*)&Ak[(gq + 8) * FSTR];
                float2 v2 = *(const float2*)&Ak[gq * FSTR + 8];
                float2 v3 = *(const float2*)&Ak[(gq + 8) * FSTR + 8];
                uint32_t a0 = pack_h2(v0.x, v0.y);
                uint32_t a1 = pack_h2(v1.x, v1.y);
                uint32_t a2 = pack_h2(v2.x, v2.y);
                uint32_t a3 = pack_h2(v3.x, v3.y);
                #pragma unroll
                for (int nb = 0; nb < 4; ++nb)
                    MMA_F16(acc[nb], a0, a1, a2, a3, bf[nb][kk][0], bf[nb][kk][1]);
            }

            // Epilogue: +base +tau*Wt (precomputed), relu, *W2, column reduce
            const float* taWj = taW[t0 + j];
            float ps_lo = 0.f, ps_hi = 0.f;
            #pragma unroll
            for (int nb = 0; nb < 4; ++nb) {
                const int c0 = wbase + nb * 8 + qd * 2;
                float2 bb = *(const float2*)&bcur[c0];
                float2 tw = *(const float2*)&taWj[c0];
                float2 w2 = *(const float2*)&W2sm[c0];
                float add0 = bb.x + tw.x;
                float add1 = bb.y + tw.y;
                ps_lo = fmaf(fmaxf(acc[nb][0] + add0, 0.f), w2.x, ps_lo);
                ps_lo = fmaf(fmaxf(acc[nb][1] + add1, 0.f), w2.y, ps_lo);
                ps_hi = fmaf(fmaxf(acc[nb][2] + add0, 0.f), w2.x, ps_hi);
                ps_hi = fmaf(fmaxf(acc[nb][3] + add1, 0.f), w2.y, ps_hi);
            }
            ps_lo += __shfl_xor_sync(0xffffffffu, ps_lo, 1);
            ps_lo += __shfl_xor_sync(0xffffffffu, ps_lo, 2);
            ps_hi += __shfl_xor_sync(0xffffffffu, ps_hi, 1);
            ps_hi += __shfl_xor_sync(0xffffffffu, ps_hi, 2);
            if (qd == 0) {
                red[j][gq][w]     = ps_lo;
                red[j][gq + 8][w] = ps_hi;
            }
        }
        __syncthreads();   // red ready + buf[cur] fully consumed

        if (tid < GQ * S_DIM) {
            const int j   = tid >> 4;
            const int row = tid & 15;
            const int g   = g0 + j;
            if (g < nGroups)
                out[(size_t)g * S_DIM + row] =
                    red[j][row][0] + red[j][row][1] +
                    red[j][row][2] + red[j][row][3] + b2v;
        }

        if (!hasNext) break;
        cur ^= 1;
        q = qn;
    }
}

// ---------------------------------------------------------------------------
extern "C" void kernel_launch(void* const* d_in, const int* in_sizes, int n_in,
                              void* d_out, int out_size)
{
    const float* h_t      = (const float*)d_in[0];
    const float* messages = (const float*)d_in[1];
    const float* tau      = (const float*)d_in[2];
    const float* theta    = (const float*)d_in[3];
    const float* W1       = (const float*)d_in[4];
    const float* b1       = (const float*)d_in[5];
    const float* W2       = (const float*)d_in[6];
    const float* b2       = (const float*)d_in[7];
    float* out = (float*)d_out;

    const int V = in_sizes[0] / NODE_DIM;
    const int nGroups = V * T_DIM;
    const int nQuads  = nGroups / GQ;

    const int smem1 = (96 * 128 + 128 + 16 * 96) * (int)sizeof(float);
    cudaFuncSetAttribute(base_kernel,
                         cudaFuncAttributeMaxDynamicSharedMemorySize, smem1);
    base_kernel<<<(V + 15) / 16, 256, smem1>>>(h_t, theta, W1, b1, V);

    // Grid = resident CTA count (persistent style).
    int nb_occ = 0, nsm = 148;
    cudaOccupancyMaxActiveBlocksPerMultiprocessor(&nb_occ, main_kernel, 128, 0);
    cudaDeviceGetAttribute(&nsm, cudaDevAttrMultiProcessorCount, 0);
    if (nb_occ < 1) nb_occ = 4;
    int grid = nb_occ * nsm;
    if (grid > nQuads) grid = nQuads;

    main_kernel<<<grid, 128>>>(messages, tau, W1, W2, b2, out, nGroups, nQuads);
}

// round 6
// speedup vs baseline: 2.0345x; 1.1131x over previous
#include <cuda_runtime.h>
#include <cstdint>

#define NODE_DIM 64
#define MSG_DIM  64
#define PROP_DIM 32
#define HIDDEN   128
#define T_DIM    8
#define S_DIM    16

#define MAX_V    10000
#define FSTR 72        // floats per A row in smem (64 + 8 pad): conflict-free LDS.64
#define GROUP_FLOATS (S_DIM * FSTR)   // 1152
#define GQ 4           // groups per CTA iteration

// Scratch: base[v][h] = h_t[v].Wh + theta[v].Wp + b1
__device__ float g_base[MAX_V * HIDDEN];

// pack two fp32 -> fp16x2 (lo = first arg), round-to-nearest-even
__device__ __forceinline__ uint32_t pack_h2(float lo, float hi) {
    uint32_t r;
    asm("cvt.rn.f16x2.f32 %0, %1, %2;" : "=r"(r) : "f"(hi), "f"(lo));
    return r;
}

#define MMA_F16(D, a0, a1, a2, a3, b0, b1)                                    \
    asm volatile(                                                             \
        "mma.sync.aligned.m16n8k16.row.col.f32.f16.f16.f32 "                  \
        "{%0,%1,%2,%3}, {%4,%5,%6,%7}, {%8,%9}, {%0,%1,%2,%3};"               \
        : "+f"(D[0]), "+f"(D[1]), "+f"(D[2]), "+f"(D[3])                      \
        : "r"(a0), "r"(a1), "r"(a2), "r"(a3), "r"(b0), "r"(b1))

__device__ __forceinline__ void cp_async16(uint32_t dst_smem, const void* src) {
    asm volatile("cp.async.cg.shared.global [%0], [%1], 16;" :: "r"(dst_smem), "l"(src));
}

// ---------------------------------------------------------------------------
// Kernel 1: base[v][h].  16 nodes per CTA, single pass.
// W1 rows: Wh = 0..63, Wm = 64..127, Wt = 128, Wp = 129..160
// ---------------------------------------------------------------------------
__global__ __launch_bounds__(256) void base_kernel(
    const float* __restrict__ h_t,
    const float* __restrict__ theta,
    const float* __restrict__ W1,
    const float* __restrict__ b1,
    int V)
{
    extern __shared__ float sm1[];
    float* Wsm  = sm1;               // 96*128
    float* b1sm = sm1 + 96 * 128;    // 128
    float* hsm  = b1sm + 128;        // 16*96

    const int tid = threadIdx.x;

    for (int i = tid; i < 96 * 128; i += 256) {
        int r = i >> 7;
        int c = i & 127;
        int gr = (r < NODE_DIM) ? r : (NODE_DIM + MSG_DIM + 1 + (r - NODE_DIM));
        Wsm[i] = W1[gr * HIDDEN + c];
    }
    if (tid < HIDDEN) b1sm[tid] = b1[tid];

    const int vp = blockIdx.x * 16;

    for (int i = tid; i < 16 * 64; i += 256) {
        int v = i >> 6, d = i & 63;
        hsm[v * 96 + d] = (vp + v < V) ? h_t[(size_t)(vp + v) * NODE_DIM + d] : 0.f;
    }
    for (int i = tid; i < 16 * 32; i += 256) {
        int v = i >> 5, p = i & 31;
        hsm[v * 96 + 64 + p] = (vp + v < V) ? theta[(size_t)(vp + v) * PROP_DIM + p] : 0.f;
    }
    __syncthreads();

    const int h4 = (tid & 31) * 4;
    const int vl = (tid >> 5) * 2;

    float4 acc0 = *(const float4*)&b1sm[h4];
    float4 acc1 = acc0;
    const float* hv0 = &hsm[vl * 96];
    const float* hv1 = hv0 + 96;

    #pragma unroll 8
    for (int d = 0; d < 96; ++d) {
        float4 ww = *(const float4*)&Wsm[d * 128 + h4];
        float x0 = hv0[d], x1 = hv1[d];
        acc0.x = fmaf(x0, ww.x, acc0.x);
        acc0.y = fmaf(x0, ww.y, acc0.y);
        acc0.z = fmaf(x0, ww.z, acc0.z);
        acc0.w = fmaf(x0, ww.w, acc0.w);
        acc1.x = fmaf(x1, ww.x, acc1.x);
        acc1.y = fmaf(x1, ww.y, acc1.y);
        acc1.z = fmaf(x1, ww.z, acc1.z);
        acc1.w = fmaf(x1, ww.w, acc1.w);
    }
    if (vp + vl < V)
        *(float4*)&g_base[(size_t)(vp + vl) * HIDDEN + h4] = acc0;
    if (vp + vl + 1 < V)
        *(float4*)&g_base[(size_t)(vp + vl + 1) * HIDDEN + h4] = acc1;
}

// ---------------------------------------------------------------------------
// Kernel 2: warp-pair fp16 mma.m16n8k16.
// Warp pair {2b, 2b+1} handles groups b and b+2 of the quad; warp 2b owns
// cols 0..63, warp 2b+1 owns cols 64..127. Wm half lives in 64 regs/warp.
// A-tile smem reads duplicated only 2x (was 4x).
// ---------------------------------------------------------------------------

__device__ __forceinline__ void stage_quad(
    float* Asb, float* bsb,
    const float* __restrict__ messages, int q, int tid)
{
    const float* msrc = messages + (size_t)q * (GQ * S_DIM * MSG_DIM);
    #pragma unroll
    for (int i = 0; i < 8; ++i) {
        int c   = tid + i * 128;      // 16B chunk index, 0..1023
        int grp = c >> 8;
        int m   = c & 255;
        int row = m >> 4;
        int cc  = m & 15;
        uint32_t dst = (uint32_t)__cvta_generic_to_shared(
            Asb + grp * GROUP_FLOATS + row * FSTR + cc * 4);
        cp_async16(dst, msrc + c * 4);
    }
    if (tid < 32) {
        int v = q >> 1;   // quad q covers groups 4q..4q+3 -> node = q/2
        uint32_t dst = (uint32_t)__cvta_generic_to_shared(bsb + tid * 4);
        cp_async16(dst, g_base + (size_t)v * HIDDEN + tid * 4);
    }
}

__global__ __launch_bounds__(128, 4) void main_kernel(
    const float* __restrict__ messages,
    const float* __restrict__ tau_values,
    const float* __restrict__ W1,
    const float* __restrict__ W2,
    const float* __restrict__ b2,
    float* __restrict__ out,
    int nGroups, int nQuads)
{
    __shared__ float As[2][GQ * GROUP_FLOATS];       // 36864 B
    __shared__ float bsm[2][HIDDEN];                 // 1024 B
    __shared__ float red[GQ][S_DIM][2];              // 512 B
    __shared__ float taW[T_DIM][HIDDEN];             // 4096 B
    __shared__ float W2sm[HIDDEN];                   // 512 B

    const int tid   = threadIdx.x;
    const int lane  = tid & 31;
    const int w     = tid >> 5;
    const int qd    = lane & 3;        // thread-in-group
    const int gq    = lane >> 2;       // row within m16 tile
    const int chalf = w & 1;           // column half: cols [chalf*64, +64)
    const int jband = w >> 1;          // groups jband, jband+2 of the quad
    const int wbase = chalf * 64;

    int q = blockIdx.x;   // grid clamped to nQuads

    stage_quad(As[0], bsm[0], messages, q, tid);
    asm volatile("cp.async.commit_group;");

    // --- Persistent B fragments (fp16x2): 8 n-blocks of this warp's half ---
    // m16n8k16 B layout: b0 = {B[kb][col], B[kb+1][col]}, b1 = rows kb+8,kb+9
    uint32_t bf[8][4][2];
    {
        const float* Wm = W1 + NODE_DIM * HIDDEN;
        #pragma unroll
        for (int nb = 0; nb < 8; ++nb) {
            const int col = wbase + nb * 8 + gq;
            #pragma unroll
            for (int kk = 0; kk < 4; ++kk) {
                const int kb = kk * 16 + 2 * qd;
                bf[nb][kk][0] = pack_h2(Wm[(kb)     * HIDDEN + col],
                                        Wm[(kb + 1) * HIDDEN + col]);
                bf[nb][kk][1] = pack_h2(Wm[(kb + 8) * HIDDEN + col],
                                        Wm[(kb + 9) * HIDDEN + col]);
            }
        }
    }

    // --- Epilogue constants in smem ---
    {
        const float* Wt = W1 + (NODE_DIM + MSG_DIM) * HIDDEN;
        float wt = Wt[tid];
        #pragma unroll
        for (int t = 0; t < T_DIM; ++t)
            taW[t][tid] = __ldg(&tau_values[t]) * wt;
        W2sm[tid] = W2[tid];
    }
    const float b2v = __ldg(&b2[0]);

    int cur = 0;
    for (;;) {
        const int qn = q + gridDim.x;
        const bool hasNext = (qn < nQuads);

        if (hasNext) {
            stage_quad(As[cur ^ 1], bsm[cur ^ 1], messages, qn, tid);
            asm volatile("cp.async.commit_group;");
            asm volatile("cp.async.wait_group 1;");
        } else {
            asm volatile("cp.async.wait_group 0;");
        }
        __syncthreads();   // buf[cur] (+ taW/W2sm on first pass) visible

        const int g0 = q * GQ;
        const int t0 = g0 & (T_DIM - 1);
        const float* bcur = bsm[cur];

        #pragma unroll
        for (int jj = 0; jj < 2; ++jj) {
            const int j = jband + 2 * jj;
            const float* Ab = &As[cur][j * GROUP_FLOATS];

            float acc[8][4];
            #pragma unroll
            for (int nb = 0; nb < 8; ++nb)
                #pragma unroll
                for (int i = 0; i < 4; ++i) acc[nb][i] = 0.f;

            #pragma unroll
            for (int kk = 0; kk < 4; ++kk) {
                const float* Ak = Ab + kk * 16 + 2 * qd;
                float2 v0 = *(const float2*)&Ak[gq * FSTR];
                float2 v1 = *(const float2*)&Ak[(gq + 8) * FSTR];
                float2 v2 = *(const float2*)&Ak[gq * FSTR + 8];
                float2 v3 = *(const float2*)&Ak[(gq + 8) * FSTR + 8];
                uint32_t a0 = pack_h2(v0.x, v0.y);
                uint32_t a1 = pack_h2(v1.x, v1.y);
                uint32_t a2 = pack_h2(v2.x, v2.y);
                uint32_t a3 = pack_h2(v3.x, v3.y);
                #pragma unroll
                for (int nb = 0; nb < 8; ++nb)
                    MMA_F16(acc[nb], a0, a1, a2, a3, bf[nb][kk][0], bf[nb][kk][1]);
            }

            // Epilogue: +base +tau*Wt (precomputed), relu, *W2, column reduce
            const float* taWj = taW[t0 + j];
            float ps_lo = 0.f, ps_hi = 0.f;
            #pragma unroll
            for (int nb = 0; nb < 8; ++nb) {
                const int c0 = wbase + nb * 8 + qd * 2;
                float2 bb = *(const float2*)&bcur[c0];
                float2 tw = *(const float2*)&taWj[c0];
                float2 w2 = *(const float2*)&W2sm[c0];
                float add0 = bb.x + tw.x;
                float add1 = bb.y + tw.y;
                ps_lo = fmaf(fmaxf(acc[nb][0] + add0, 0.f), w2.x, ps_lo);
                ps_lo = fmaf(fmaxf(acc[nb][1] + add1, 0.f), w2.y, ps_lo);
                ps_hi = fmaf(fmaxf(acc[nb][2] + add0, 0.f), w2.x, ps_hi);
                ps_hi = fmaf(fmaxf(acc[nb][3] + add1, 0.f), w2.y, ps_hi);
            }
            ps_lo += __shfl_xor_sync(0xffffffffu, ps_lo, 1);
            ps_lo += __shfl_xor_sync(0xffffffffu, ps_lo, 2);
            ps_hi += __shfl_xor_sync(0xffffffffu, ps_hi, 1);
            ps_hi += __shfl_xor_sync(0xffffffffu, ps_hi, 2);
            if (qd == 0) {
                red[j][gq][chalf]     = ps_lo;
                red[j][gq + 8][chalf] = ps_hi;
            }
        }
        __syncthreads();   // red ready + buf[cur] fully consumed

        if (tid < GQ * S_DIM) {
            const int j   = tid >> 4;
            const int row = tid & 15;
            const int g   = g0 + j;
            if (g < nGroups)
                out[(size_t)g * S_DIM + row] =
                    red[j][row][0] + red[j][row][1] + b2v;
        }

        if (!hasNext) break;
        cur ^= 1;
        q = qn;
    }
}

// ---------------------------------------------------------------------------
extern "C" void kernel_launch(void* const* d_in, const int* in_sizes, int n_in,
                              void* d_out, int out_size)
{
    const float* h_t      = (const float*)d_in[0];
    const float* messages = (const float*)d_in[1];
    const float* tau      = (const float*)d_in[2];
    const float* theta    = (const float*)d_in[3];
    const float* W1       = (const float*)d_in[4];
    const float* b1       = (const float*)d_in[5];
    const float* W2       = (const float*)d_in[6];
    const float* b2       = (const float*)d_in[7];
    float* out = (float*)d_out;

    const int V = in_sizes[0] / NODE_DIM;
    const int nGroups = V * T_DIM;
    const int nQuads  = nGroups / GQ;

    const int smem1 = (96 * 128 + 128 + 16 * 96) * (int)sizeof(float);
    cudaFuncSetAttribute(base_kernel,
                         cudaFuncAttributeMaxDynamicSharedMemorySize, smem1);
    base_kernel<<<(V + 15) / 16, 256, smem1>>>(h_t, theta, W1, b1, V);

    // Grid = resident CTA count (persistent style).
    int nb_occ = 0, nsm = 148;
    cudaOccupancyMaxActiveBlocksPerMultiprocessor(&nb_occ, main_kernel, 128, 0);
    cudaDeviceGetAttribute(&nsm, cudaDevAttrMultiProcessorCount, 0);
    if (nb_occ < 1) nb_occ = 4;
    int grid = nb_occ * nsm;
    if (grid > nQuads) grid = nQuads;

    main_kernel<<<grid, 128>>>(messages, tau, W1, W2, b2, out, nGroups, nQuads);
}

// round 7
// speedup vs baseline: 2.0577x; 1.0114x over previous
#include <cuda_runtime.h>
#include <cstdint>

#define NODE_DIM 64
#define MSG_DIM  64
#define PROP_DIM 32
#define HIDDEN   128
#define T_DIM    8
#define S_DIM    16

#define MAX_V    10000
#define GQ 4             // groups per CTA iteration
#define HSTR 72          // halfs per A row in smem (64 + 8 pad) -> 144B stride
#define GROUP_HALFS (S_DIM * HSTR)     // 1152 halfs = 2304 B per group

// Scratch: base[v][h] = h_t[v].Wh + theta[v].Wp + b1
__device__ float g_base[MAX_V * HIDDEN];

// pack two fp32 -> fp16x2 (lo = first arg), round-to-nearest-even
__device__ __forceinline__ uint32_t pack_h2(float lo, float hi) {
    uint32_t r;
    asm("cvt.rn.f16x2.f32 %0, %1, %2;" : "=r"(r) : "f"(hi), "f"(lo));
    return r;
}

#define MMA_F16(D, a0, a1, a2, a3, b0, b1)                                    \
    asm volatile(                                                             \
        "mma.sync.aligned.m16n8k16.row.col.f32.f16.f16.f32 "                  \
        "{%0,%1,%2,%3}, {%4,%5,%6,%7}, {%8,%9}, {%0,%1,%2,%3};"               \
        : "+f"(D[0]), "+f"(D[1]), "+f"(D[2]), "+f"(D[3])                      \
        : "r"(a0), "r"(a1), "r"(a2), "r"(a3), "r"(b0), "r"(b1))

#define LDMATRIX_X4(a0, a1, a2, a3, addr)                                     \
    asm volatile(                                                             \
        "ldmatrix.sync.aligned.m8n8.x4.shared.b16 {%0,%1,%2,%3}, [%4];"       \
        : "=r"(a0), "=r"(a1), "=r"(a2), "=r"(a3) : "r"(addr))

// ---------------------------------------------------------------------------
// Kernel 1: base[v][h].  16 nodes per CTA, single pass.
// W1 rows: Wh = 0..63, Wm = 64..127, Wt = 128, Wp = 129..160
// ---------------------------------------------------------------------------
__global__ __launch_bounds__(256) void base_kernel(
    const float* __restrict__ h_t,
    const float* __restrict__ theta,
    const float* __restrict__ W1,
    const float* __restrict__ b1,
    int V)
{
    extern __shared__ float sm1[];
    float* Wsm  = sm1;               // 96*128
    float* b1sm = sm1 + 96 * 128;    // 128
    float* hsm  = b1sm + 128;        // 16*96

    const int tid = threadIdx.x;

    for (int i = tid; i < 96 * 128; i += 256) {
        int r = i >> 7;
        int c = i & 127;
        int gr = (r < NODE_DIM) ? r : (NODE_DIM + MSG_DIM + 1 + (r - NODE_DIM));
        Wsm[i] = W1[gr * HIDDEN + c];
    }
    if (tid < HIDDEN) b1sm[tid] = b1[tid];

    const int vp = blockIdx.x * 16;

    for (int i = tid; i < 16 * 64; i += 256) {
        int v = i >> 6, d = i & 63;
        hsm[v * 96 + d] = (vp + v < V) ? h_t[(size_t)(vp + v) * NODE_DIM + d] : 0.f;
    }
    for (int i = tid; i < 16 * 32; i += 256) {
        int v = i >> 5, p = i & 31;
        hsm[v * 96 + 64 + p] = (vp + v < V) ? theta[(size_t)(vp + v) * PROP_DIM + p] : 0.f;
    }
    __syncthreads();

    const int h4 = (tid & 31) * 4;
    const int vl = (tid >> 5) * 2;

    float4 acc0 = *(const float4*)&b1sm[h4];
    float4 acc1 = acc0;
    const float* hv0 = &hsm[vl * 96];
    const float* hv1 = hv0 + 96;

    #pragma unroll 8
    for (int d = 0; d < 96; ++d) {
        float4 ww = *(const float4*)&Wsm[d * 128 + h4];
        float x0 = hv0[d], x1 = hv1[d];
        acc0.x = fmaf(x0, ww.x, acc0.x);
        acc0.y = fmaf(x0, ww.y, acc0.y);
        acc0.z = fmaf(x0, ww.z, acc0.z);
        acc0.w = fmaf(x0, ww.w, acc0.w);
        acc1.x = fmaf(x1, ww.x, acc1.x);
        acc1.y = fmaf(x1, ww.y, acc1.y);
        acc1.z = fmaf(x1, ww.z, acc1.z);
        acc1.w = fmaf(x1, ww.w, acc1.w);
    }
    if (vp + vl < V)
        *(float4*)&g_base[(size_t)(vp + vl) * HIDDEN + h4] = acc0;
    if (vp + vl + 1 < V)
        *(float4*)&g_base[(size_t)(vp + vl + 1) * HIDDEN + h4] = acc1;
}

// ---------------------------------------------------------------------------
// Kernel 2: fp16-smem + ldmatrix warp-pair mma.m16n8k16.
// Stage: LDG.128 fp32 (reg-prefetched 1 quad ahead) -> cvt.rn.f16x2 -> STS.64.
// Mainloop: 1 ldmatrix.x4 per kk per warp; Wm half in 64 regs/warp.
// ---------------------------------------------------------------------------

__global__ __launch_bounds__(128, 3) void main_kernel(
    const float* __restrict__ messages,
    const float* __restrict__ tau_values,
    const float* __restrict__ W1,
    const float* __restrict__ W2,
    const float* __restrict__ b2,
    float* __restrict__ out,
    int nGroups, int nQuads)
{
    __shared__ uint32_t As32[GQ * GROUP_HALFS / 2];  // 9216 B, fp16 A quad
    __shared__ float bsm[HIDDEN];                    // 512 B
    __shared__ float red[GQ][S_DIM][2];              // 512 B
    __shared__ float taW[T_DIM][HIDDEN];             // 4096 B
    __shared__ float W2sm[HIDDEN];                   // 512 B

    const int tid   = threadIdx.x;
    const int lane  = tid & 31;
    const int w     = tid >> 5;
    const int qd    = lane & 3;        // thread-in-group
    const int gq    = lane >> 2;       // row within m16 tile
    const int chalf = w & 1;           // column half: cols [chalf*64, +64)
    const int jband = w >> 1;          // groups jband, jband+2 of the quad
    const int wbase = chalf * 64;

    // --- Persistent B fragments (fp16x2): 8 n-blocks of this warp's half ---
    uint32_t bf[8][4][2];
    {
        const float* Wm = W1 + NODE_DIM * HIDDEN;
        #pragma unroll
        for (int nb = 0; nb < 8; ++nb) {
            const int col = wbase + nb * 8 + gq;
            #pragma unroll
            for (int kk = 0; kk < 4; ++kk) {
                const int kb = kk * 16 + 2 * qd;
                bf[nb][kk][0] = pack_h2(Wm[(kb)     * HIDDEN + col],
                                        Wm[(kb + 1) * HIDDEN + col]);
                bf[nb][kk][1] = pack_h2(Wm[(kb + 8) * HIDDEN + col],
                                        Wm[(kb + 9) * HIDDEN + col]);
            }
        }
    }

    // --- Epilogue constants in smem ---
    {
        const float* Wt = W1 + (NODE_DIM + MSG_DIM) * HIDDEN;
        float wt = Wt[tid];
        #pragma unroll
        for (int t = 0; t < T_DIM; ++t)
            taW[t][tid] = __ldg(&tau_values[t]) * wt;
        W2sm[tid] = W2[tid];
    }
    const float b2v = __ldg(&b2[0]);

    // Per-thread staging geometry: chunk c = tid + i*128 (16B fp32 chunks)
    //   grp = c>>8, m = c&255, row = m>>4, c4 = m&15
    //   smem uint32 index = grp*576 + row*36 + c4*2
    // ldmatrix base address for this thread (bytes):
    const uint32_t As_base = (uint32_t)__cvta_generic_to_shared(As32);
    const uint32_t lm_off  = (uint32_t)((lane & 15) * (HSTR * 2) + ((lane >> 4) & 1) * 16);

    int q = blockIdx.x;   // grid clamped to nQuads

    // --- Prologue: prefetch first quad into registers ---
    float4 st[8];
    float4 bb = make_float4(0.f, 0.f, 0.f, 0.f);
    {
        const float4* msrc = (const float4*)(messages + (size_t)q * (GQ * S_DIM * MSG_DIM));
        #pragma unroll
        for (int i = 0; i < 8; ++i) st[i] = msrc[tid + i * 128];
        if (tid < 32) bb = ((const float4*)(g_base + (size_t)(q >> 1) * HIDDEN))[tid];
    }

    for (;;) {
        const int qn = q + gridDim.x;
        const bool hasNext = (qn < nQuads);

        // --- Stage current quad: pack fp32 regs -> fp16 smem ---
        #pragma unroll
        for (int i = 0; i < 8; ++i) {
            const int c   = tid + i * 128;
            const int grp = c >> 8;
            const int m   = c & 255;
            const int row = m >> 4;
            const int c4  = m & 15;
            uint2 pk;
            pk.x = pack_h2(st[i].x, st[i].y);
            pk.y = pack_h2(st[i].z, st[i].w);
            *(uint2*)&As32[grp * 576 + row * 36 + c4 * 2] = pk;
        }
        if (tid < 32) *(float4*)&bsm[tid * 4] = bb;

        // --- Prefetch next quad (LDG latency hidden under MMA phase) ---
        if (hasNext) {
            const float4* msrc = (const float4*)(messages + (size_t)qn * (GQ * S_DIM * MSG_DIM));
            #pragma unroll
            for (int i = 0; i < 8; ++i) st[i] = msrc[tid + i * 128];
            if (tid < 32) bb = ((const float4*)(g_base + (size_t)(qn >> 1) * HIDDEN))[tid];
        }
        __syncthreads();   // staged quad visible (taW/W2sm on first pass too)

        const int g0 = q * GQ;
        const int t0 = g0 & (T_DIM - 1);

        #pragma unroll
        for (int jj = 0; jj < 2; ++jj) {
            const int j = jband + 2 * jj;
            const uint32_t Aaddr = As_base + (uint32_t)(j * (GROUP_HALFS * 2)) + lm_off;

            float acc[8][4];
            #pragma unroll
            for (int nb = 0; nb < 8; ++nb)
                #pragma unroll
                for (int i = 0; i < 4; ++i) acc[nb][i] = 0.f;

            #pragma unroll
            for (int kk = 0; kk < 4; ++kk) {
                uint32_t a0, a1, a2, a3;
                LDMATRIX_X4(a0, a1, a2, a3, Aaddr + kk * 32);
                #pragma unroll
                for (int nb = 0; nb < 8; ++nb)
                    MMA_F16(acc[nb], a0, a1, a2, a3, bf[nb][kk][0], bf[nb][kk][1]);
            }

            // Epilogue: +base +tau*Wt (precomputed), relu, *W2, column reduce
            const float* taWj = taW[t0 + j];
            float ps_lo = 0.f, ps_hi = 0.f;
            #pragma unroll
            for (int nb = 0; nb < 8; ++nb) {
                const int c0 = wbase + nb * 8 + qd * 2;
                float2 b2f = *(const float2*)&bsm[c0];
                float2 tw  = *(const float2*)&taWj[c0];
                float2 w2  = *(const float2*)&W2sm[c0];
                float add0 = b2f.x + tw.x;
                float add1 = b2f.y + tw.y;
                ps_lo = fmaf(fmaxf(acc[nb][0] + add0, 0.f), w2.x, ps_lo);
                ps_lo = fmaf(fmaxf(acc[nb][1] + add1, 0.f), w2.y, ps_lo);
                ps_hi = fmaf(fmaxf(acc[nb][2] + add0, 0.f), w2.x, ps_hi);
                ps_hi = fmaf(fmaxf(acc[nb][3] + add1, 0.f), w2.y, ps_hi);
            }
            ps_lo += __shfl_xor_sync(0xffffffffu, ps_lo, 1);
            ps_lo += __shfl_xor_sync(0xffffffffu, ps_lo, 2);
            ps_hi += __shfl_xor_sync(0xffffffffu, ps_hi, 1);
            ps_hi += __shfl_xor_sync(0xffffffffu, ps_hi, 2);
            if (qd == 0) {
                red[j][gq][chalf]     = ps_lo;
                red[j][gq + 8][chalf] = ps_hi;
            }
        }
        __syncthreads();   // red ready + As/bsm fully consumed

        if (tid < GQ * S_DIM) {
            const int j   = tid >> 4;
            const int row = tid & 15;
            const int g   = g0 + j;
            if (g < nGroups)
                out[(size_t)g * S_DIM + row] =
                    red[j][row][0] + red[j][row][1] + b2v;
        }
        // out-reads of red complete before the next iteration's red writes,
        // which are ordered behind the next first __syncthreads().

        if (!hasNext) break;
        q = qn;
    }
}

// ---------------------------------------------------------------------------
extern "C" void kernel_launch(void* const* d_in, const int* in_sizes, int n_in,
                              void* d_out, int out_size)
{
    const float* h_t      = (const float*)d_in[0];
    const float* messages = (const float*)d_in[1];
    const float* tau      = (const float*)d_in[2];
    const float* theta    = (const float*)d_in[3];
    const float* W1       = (const float*)d_in[4];
    const float* b1       = (const float*)d_in[5];
    const float* W2       = (const float*)d_in[6];
    const float* b2       = (const float*)d_in[7];
    float* out = (float*)d_out;

    const int V = in_sizes[0] / NODE_DIM;
    const int nGroups = V * T_DIM;
    const int nQuads  = nGroups / GQ;

    const int smem1 = (96 * 128 + 128 + 16 * 96) * (int)sizeof(float);
    cudaFuncSetAttribute(base_kernel,
                         cudaFuncAttributeMaxDynamicSharedMemorySize, smem1);
    base_kernel<<<(V + 15) / 16, 256, smem1>>>(h_t, theta, W1, b1, V);

    // Grid = resident CTA count (persistent style).
    int nb_occ = 0, nsm = 148;
    cudaOccupancyMaxActiveBlocksPerMultiprocessor(&nb_occ, main_kernel, 128, 0);
    cudaDeviceGetAttribute(&nsm, cudaDevAttrMultiProcessorCount, 0);
    if (nb_occ < 1) nb_occ = 3;
    int grid = nb_occ * nsm;
    if (grid > nQuads) grid = nQuads;

    main_kernel<<<grid, 128>>>(messages, tau, W1, W2, b2, out, nGroups, nQuads);
}